// round 14
// baseline (speedup 1.0000x reference)
#include <cuda_runtime.h>
#include <cuda_bf16.h>
#include <math.h>
#include <stdint.h>

#define D_MODEL 512
#define D_LOW   64
#define NUM_BINS 39
#define NB_PAD  40
#define DIST_MIN_F 2.0f
#define DIST_MAX_F 22.0f
#define BIN_W  ((DIST_MAX_F - DIST_MIN_F) / (float)(NUM_BINS - 1))
#define LN_EPS 1e-5f
#define MAX_ROWS 4096
#define JT 128
#define TOK 4                  // tokens per CTA (main)
#define TR 16                  // rows per CTA (prep)
#define CHK 128                // channel chunk (prep weight tile)

__device__ float g_U[MAX_ROWS * D_LOW];
__device__ unsigned long long g_Vb[MAX_ROWS * (D_LOW / 4)];  // 4 bf16 per u64
__device__ double g_ce[8];
__device__ unsigned int g_cnt[8];
__device__ unsigned int g_done;

#define CVT_BF2(res, lo, hi) \
    asm("cvt.rn.satfinite.bf16x2.f32 %0, %1, %2;" : "=r"(res) : "f"(hi), "f"(lo))
#define MULBF2(res, a, b) \
    asm("mul.bf16x2 %0, %1, %2;" : "=r"(res) : "r"(a), "r"(b))

#define MMA_BF16(d, a0, a1, a2, a3, b0, b1) \
    asm volatile("mma.sync.aligned.m16n8k16.row.col.f32.bf16.bf16.f32 " \
                 "{%0,%1,%2,%3}, {%4,%5,%6,%7}, {%8,%9}, {%0,%1,%2,%3};" \
                 : "+f"((d)[0]), "+f"((d)[1]), "+f"((d)[2]), "+f"((d)[3]) \
                 : "r"(a0), "r"(a1), "r"(a2), "r"(a3), "r"(b0), "r"(b1))

// ---------------------------------------------------------------------------
// Kernel 1: LayerNorm + projections with in-kernel weight transpose
// (unchanged from R13). grid = (BN/16)*2; half 0 -> U fp32, half 1 -> V bf16.
// ---------------------------------------------------------------------------
extern __shared__ float prep_dsm[];

__global__ void __launch_bounds__(256) prep_kernel(
    const float* __restrict__ h_res,
    const float* __restrict__ ln_w, const float* __restrict__ ln_b,
    const float* __restrict__ wu_w, const float* __restrict__ wu_b,
    const float* __restrict__ wv_w, const float* __restrict__ wv_b)
{
    float* sh = prep_dsm;                 // 16*512 floats
    float* Ws = prep_dsm + TR * D_MODEL;  // CHK*68 floats

    int t    = threadIdx.x;
    int warp = t >> 5;
    int lane = t & 31;
    int rb   = blockIdx.x >> 1;
    int half = blockIdx.x & 1;

    if (blockIdx.x == 0) {
        if (t < 8) { g_ce[t] = 0.0; g_cnt[t] = 0u; }
        if (t == 8) g_done = 0u;
    }

    #pragma unroll
    for (int rr = 0; rr < 2; rr++) {
        int lr  = warp * 2 + rr;
        size_t row = (size_t)rb * TR + lr;
        const float4* hp = reinterpret_cast<const float4*>(h_res) + row * (D_MODEL / 4);
        float4 a[4];
        #pragma unroll
        for (int q = 0; q < 4; q++) a[q] = hp[lane + 32 * q];
        float s = 0.0f, sq = 0.0f;
        #pragma unroll
        for (int q = 0; q < 4; q++) {
            s  += a[q].x + a[q].y + a[q].z + a[q].w;
            sq += a[q].x*a[q].x + a[q].y*a[q].y + a[q].z*a[q].z + a[q].w*a[q].w;
        }
        #pragma unroll
        for (int o = 16; o > 0; o >>= 1) {
            s  += __shfl_xor_sync(0xffffffffu, s,  o);
            sq += __shfl_xor_sync(0xffffffffu, sq, o);
        }
        float mu   = s * (1.0f / (float)D_MODEL);
        float var  = sq * (1.0f / (float)D_MODEL) - mu * mu;
        float istd = rsqrtf(var + LN_EPS);

        const float4* wp = reinterpret_cast<const float4*>(ln_w);
        const float4* bp = reinterpret_cast<const float4*>(ln_b);
        float4* shp = reinterpret_cast<float4*>(sh) + lr * (D_MODEL / 4);
        #pragma unroll
        for (int q = 0; q < 4; q++) {
            float4 w4 = wp[lane + 32 * q];
            float4 b4 = bp[lane + 32 * q];
            float4 nv;
            nv.x = (a[q].x - mu) * istd * w4.x + b4.x;
            nv.y = (a[q].y - mu) * istd * w4.y + b4.y;
            nv.z = (a[q].z - mu) * istd * w4.z + b4.z;
            nv.w = (a[q].w - mu) * istd * w4.w + b4.w;
            shp[lane + 32 * q] = nv;
        }
    }
    __syncthreads();

    const float* wsrc = (half == 0) ? wu_w : wv_w;
    int ty = t >> 4;
    int tx = t & 15;

    float a0 = 0.0f, a1 = 0.0f, a2 = 0.0f, a3 = 0.0f;

    for (int cc = 0; cc < D_MODEL; cc += CHK) {
        #pragma unroll
        for (int it = 0; it < (D_LOW * CHK) / 256; it++) {
            int idx = t + it * 256;
            int c = idx & (CHK - 1);
            int o = idx >> 7;
            Ws[c * 68 + o] = wsrc[(size_t)o * D_MODEL + cc + c];
        }
        __syncthreads();

        const float* shr = sh + ty * D_MODEL + cc;
        #pragma unroll 4
        for (int c = 0; c < CHK; c++) {
            float4 w = *reinterpret_cast<const float4*>(Ws + c * 68 + tx * 4);
            float h = shr[c];
            a0 = fmaf(h, w.x, a0);
            a1 = fmaf(h, w.y, a1);
            a2 = fmaf(h, w.z, a2);
            a3 = fmaf(h, w.w, a3);
        }
        __syncthreads();
    }

    size_t grow = (size_t)rb * TR + ty;
    int lcol = tx * 4;
    if (half == 0) {
        float4 b = *reinterpret_cast<const float4*>(wu_b + lcol);
        *reinterpret_cast<float4*>(g_U + grow * D_LOW + lcol) =
            make_float4(a0 + b.x, a1 + b.y, a2 + b.z, a3 + b.w);
    } else {
        float4 b = *reinterpret_cast<const float4*>(wv_b + lcol);
        float v0 = a0 + b.x, v1 = a1 + b.y, v2 = a2 + b.z, v3 = a3 + b.w;
        uint32_t lo, hi;
        CVT_BF2(lo, v0, v1); CVT_BF2(hi, v2, v3);
        g_Vb[grow * 16 + (lcol >> 2)] = (unsigned long long)lo | ((unsigned long long)hi << 32);
    }
}

// ---------------------------------------------------------------------------
// Kernel 2: mma.sync bilinear. Grid doubled via j-split (each CTA does half
// the chunks) and B-fragments moved to conflict-free permuted smem (volatile
// reads) to cut registers -> 4 CTAs/SM. TOK=4 tokens share each V chunk.
// ---------------------------------------------------------------------------
#define DSTRIDE 41            // floats per D row (odd -> conflict-free scalar LDS)
#define VW 36                 // words per s_V row (9 uint4)

__global__ void __launch_bounds__(128, 4) main_kernel(
    const float* __restrict__ x_true, const float* __restrict__ pad,
    const float* __restrict__ wb_w,  const float* __restrict__ wb_b,
    int B, int N, float* __restrict__ out, int total_ctas)
{
    __shared__ uint4 s_V[JT * 9];                 // 18432 B
    __shared__ float s_D[4][32 * DSTRIDE];        // 20992 B
    __shared__ uint32_t s_Bf[2 * 16 * NB_PAD];    // 5120 B permuted B-fragments
    __shared__ uint32_t s_U[TOK * 32];            // tokens x 32 bf16x2
    __shared__ float s_wbb[NB_PAD];
    __shared__ float s_xi[TOK * 4];
    __shared__ float s_red[4];
    __shared__ unsigned s_redc[4];

    int tid  = threadIdx.x;
    int wid  = tid >> 5;
    int lane = tid & 31;
    int g    = lane >> 2;       // group row (0..7)
    int tig  = lane & 3;        // thread in group (0..3)
    int tb    = blockIdx.x >> 1;   // token block
    int jhalf = blockIdx.x & 1;    // which half of the j-chunks
    int r0 = tb * TOK;             // first token row (b*N + i); N % TOK == 0
    int b  = r0 / N;

    // B-fragment table: s_Bf[w][ks*4+tig][nt*8+g]; bank = (8*tig+g)%32 ->
    // bijective over the 32 lanes => conflict-free.
    for (int idx = tid; idx < 2 * 16 * NB_PAD; idx += 128) {
        int w   = idx / (16 * NB_PAD);
        int rem = idx % (16 * NB_PAD);
        int kt  = rem / NB_PAD;       // ks*4+tig
        int col = rem % NB_PAD;       // nt*8+g  (= bin row)
        int ks  = kt >> 2, tg = kt & 3;
        int cp  = ks * 8 + tg + w * 4;
        float f0 = 0.0f, f1 = 0.0f;
        if (col < NUM_BINS) {
            f0 = wb_w[col * D_LOW + cp * 2];
            f1 = wb_w[col * D_LOW + cp * 2 + 1];
        }
        uint32_t v; CVT_BF2(v, f0, f1);
        s_Bf[idx] = v;
    }
    if (tid < TOK * 32) {
        int tok = tid >> 5, w = tid & 31;
        float f0 = g_U[(size_t)(r0 + tok) * D_LOW + w * 2];
        float f1 = g_U[(size_t)(r0 + tok) * D_LOW + w * 2 + 1];
        uint32_t v; CVT_BF2(v, f0, f1);
        s_U[tid] = v;
    }
    if (tid < NB_PAD) s_wbb[tid] = (tid < NUM_BINS) ? wb_b[tid] : 0.0f;
    if (tid < TOK) {
        size_t xb = (size_t)(r0 + tid) * 3;
        s_xi[tid * 4 + 0] = x_true[xb];
        s_xi[tid * 4 + 1] = x_true[xb + 1];
        s_xi[tid * 4 + 2] = x_true[xb + 2];
        s_xi[tid * 4 + 3] = pad[r0 + tid];
    }
    __syncthreads();

    // bias for this lane's D columns
    float bias0[5], bias1[5];
    #pragma unroll
    for (int nt = 0; nt < 5; nt++) {
        bias0[nt] = s_wbb[nt * 8 + 2 * tig];
        bias1[nt] = s_wbb[nt * 8 + 2 * tig + 1];
    }

    float* sDw = s_D[wid];
    const uint32_t* sv32 = reinterpret_cast<const uint32_t*>(s_V);
    volatile const uint32_t* vBf = s_Bf;   // volatile: keep B-frags in smem

    float cv = 0.0f; unsigned cc = 0u;
    int nchunks = (N + JT - 1) / JT;
    int nch2 = (nchunks + 1) >> 1;
    int jstart = jhalf * nch2;
    int jend = min(nchunks, jstart + nch2);

    for (int jc = jstart; jc < jend; jc++) {
        __syncwarp();
        int jw = jc * JT + wid * 32;      // this warp's first j

        // stage V rows jw..jw+31 (coalesced: 8 lanes per 128B row)
        {
            const uint4* src = reinterpret_cast<const uint4*>(g_Vb) + ((size_t)b * N) * 8;
            #pragma unroll
            for (int it = 0; it < 8; it++) {
                int idx = it * 32 + lane;
                int row = idx >> 3, q = idx & 7;
                int j = jw + row;
                uint4 v = make_uint4(0u, 0u, 0u, 0u);
                if (j < N) v = src[(size_t)j * 8 + q];
                s_V[(wid * 32 + row) * 9 + q] = v;
            }
        }

        // j-coordinates loaded once, reused by all tokens
        int j = jw + lane;
        float xj0 = 0.f, xj1 = 0.f, xj2 = 0.f, pj = 0.f;
        if (j < N) {
            size_t xb = ((size_t)b * N + j) * 3;
            xj0 = x_true[xb]; xj1 = x_true[xb + 1]; xj2 = x_true[xb + 2];
            pj = pad[(size_t)b * N + j];
        }
        __syncwarp();

        #pragma unroll
        for (int tok = 0; tok < TOK; tok++) {
            // U words for this token
            uint32_t ureg[8];
            #pragma unroll
            for (int ks = 0; ks < 4; ks++) {
                ureg[2 * ks + 0] = s_U[tok * 32 + ks * 8 + tig];
                ureg[2 * ks + 1] = s_U[tok * 32 + ks * 8 + tig + 4];
            }

            // acc init = bias
            float acc[2][5][4];
            #pragma unroll
            for (int m = 0; m < 2; m++)
                #pragma unroll
                for (int nt = 0; nt < 5; nt++) {
                    acc[m][nt][0] = bias0[nt];
                    acc[m][nt][1] = bias1[nt];
                    acc[m][nt][2] = bias0[nt];
                    acc[m][nt][3] = bias1[nt];
                }

            // ks outer: B-frags loaded once per ks (volatile, conflict-free),
            // shared across both m-tiles.
            #pragma unroll
            for (int ks = 0; ks < 4; ks++) {
                uint32_t b0[5], b1[5];
                int bbase = (ks * 4 + tig) * NB_PAD + g;
                #pragma unroll
                for (int nt = 0; nt < 5; nt++) {
                    b0[nt] = vBf[bbase + nt * 8];
                    b1[nt] = vBf[16 * NB_PAD + bbase + nt * 8];
                }
                #pragma unroll
                for (int m = 0; m < 2; m++) {
                    int row0 = wid * 32 + m * 16 + g;
                    int w0 = row0 * VW + ks * 8 + tig;
                    uint32_t a0 = sv32[w0];
                    uint32_t a1 = sv32[w0 + 8 * VW];
                    uint32_t a2 = sv32[w0 + 4];
                    uint32_t a3 = sv32[w0 + 8 * VW + 4];
                    MULBF2(a0, a0, ureg[2 * ks]);
                    MULBF2(a1, a1, ureg[2 * ks]);
                    MULBF2(a2, a2, ureg[2 * ks + 1]);
                    MULBF2(a3, a3, ureg[2 * ks + 1]);
                    #pragma unroll
                    for (int nt = 0; nt < 5; nt++)
                        MMA_BF16(acc[m][nt], a0, a1, a2, a3, b0[nt], b1[nt]);
                }
            }
            __syncwarp();

            // D -> smem (pair-major, 41-float stride)
            #pragma unroll
            for (int m = 0; m < 2; m++) {
                int p0 = m * 16 + g;
                #pragma unroll
                for (int nt = 0; nt < 5; nt++) {
                    int col = nt * 8 + tig * 2;
                    sDw[p0 * DSTRIDE + col]           = acc[m][nt][0];
                    sDw[p0 * DSTRIDE + col + 1]       = acc[m][nt][1];
                    sDw[(p0 + 8) * DSTRIDE + col]     = acc[m][nt][2];
                    sDw[(p0 + 8) * DSTRIDE + col + 1] = acc[m][nt][3];
                }
            }
            __syncwarp();

            // epilogue: pair = lane, single-pass maxless logsumexp
            const float* lrow = sDw + lane * DSTRIDE;
            float xi0 = s_xi[tok * 4 + 0];
            float xi1 = s_xi[tok * 4 + 1];
            float xi2 = s_xi[tok * 4 + 2];
            float pi  = s_xi[tok * 4 + 3];
            float dx = xi0 - xj0, dy = xi1 - xj1, dz = xi2 - xj2;
            float dist = sqrtf(dx * dx + dy * dy + dz * dz);
            int bin = (int)((dist - DIST_MIN_F) / BIN_W);
            bin = min(max(bin, 0), NUM_BINS - 1);

            float ssum = 0.0f, tl = 0.0f;
            #pragma unroll
            for (int k = 0; k < NUM_BINS; k++) {
                float lv = lrow[k];
                ssum += __expf(lv);
                if (k == bin) tl = lv;
            }
            float ce = __logf(ssum) - tl;

            bool ok = (j < N) && (pi * pj > 0.0f);
            cv += ok ? ce : 0.0f;
            cc += ok ? 1u : 0u;
            __syncwarp();
        }
    }

    #pragma unroll
    for (int o = 16; o > 0; o >>= 1) {
        cv += __shfl_down_sync(0xffffffffu, cv, o);
        cc += __shfl_down_sync(0xffffffffu, cc, o);
    }
    if (lane == 0) { s_red[wid] = cv; s_redc[wid] = cc; }
    __syncthreads();
    if (tid == 0) {
        float S = s_red[0] + s_red[1] + s_red[2] + s_red[3];
        unsigned C = s_redc[0] + s_redc[1] + s_redc[2] + s_redc[3];
        atomicAdd(&g_ce[b], (double)S);
        atomicAdd(&g_cnt[b], C);
        __threadfence();
        unsigned done = atomicAdd(&g_done, 1u);
        if (done == (unsigned)(total_ctas - 1)) {
            __threadfence();
            double loss = 0.0;
            int valid = 0;
            for (int bb = 0; bb < B; bb++) {
                if (g_cnt[bb] > 0u) { loss += g_ce[bb] / (double)g_cnt[bb]; valid++; }
            }
            out[0] = (float)(valid > 0 ? loss / (double)valid : 0.0);
        }
    }
}

// ---------------------------------------------------------------------------
extern "C" void kernel_launch(void* const* d_in, const int* in_sizes, int n_in,
                              void* d_out, int out_size)
{
    const float* h_res  = (const float*)d_in[0];
    const float* x_true = (const float*)d_in[1];
    const float* padm   = (const float*)d_in[2];
    const float* ln_w   = (const float*)d_in[3];
    const float* ln_b   = (const float*)d_in[4];
    const float* wu_w   = (const float*)d_in[5];
    const float* wu_b   = (const float*)d_in[6];
    const float* wv_w   = (const float*)d_in[7];
    const float* wv_b   = (const float*)d_in[8];
    const float* wb_w   = (const float*)d_in[9];
    const float* wb_b   = (const float*)d_in[10];

    int BN = in_sizes[0] / D_MODEL;   // B*N
    int B = 2;
    int N = BN / B;

    const int prep_smem = (TR * D_MODEL + CHK * 68) * (int)sizeof(float);  // ~67.6 KB
    cudaFuncSetAttribute(prep_kernel, cudaFuncAttributeMaxDynamicSharedMemorySize, prep_smem);

    prep_kernel<<<(BN / TR) * 2, 256, prep_smem>>>(h_res, ln_w, ln_b,
                                                   wu_w, wu_b, wv_w, wv_b);

    int mgrid = (BN / TOK) * 2;   // j-split doubles the grid
    main_kernel<<<mgrid, 128>>>(x_true, padm, wb_w, wb_b, B, N, (float*)d_out, mgrid);
}

// round 15
// speedup vs baseline: 1.0888x; 1.0888x over previous
#include <cuda_runtime.h>
#include <cuda_bf16.h>
#include <math.h>
#include <stdint.h>

#define D_MODEL 512
#define D_LOW   64
#define NUM_BINS 39
#define NB_PAD  40
#define DIST_MIN_F 2.0f
#define DIST_MAX_F 22.0f
#define BIN_W  ((DIST_MAX_F - DIST_MIN_F) / (float)(NUM_BINS - 1))
#define LN_EPS 1e-5f
#define MAX_ROWS 4096
#define JT 128
#define TOK 4                  // tokens per CTA (main)
#define TR 8                   // rows per CTA (prep)
#define CHK 128                // channel chunk (prep weight tile)

__device__ float g_U[MAX_ROWS * D_LOW];
__device__ unsigned long long g_Vb[MAX_ROWS * (D_LOW / 4)];  // 4 bf16 per u64
__device__ double g_ce[8];
__device__ unsigned int g_cnt[8];
__device__ unsigned int g_done;

#define CVT_BF2(res, lo, hi) \
    asm("cvt.rn.satfinite.bf16x2.f32 %0, %1, %2;" : "=r"(res) : "f"(hi), "f"(lo))
#define MULBF2(res, a, b) \
    asm("mul.bf16x2 %0, %1, %2;" : "=r"(res) : "r"(a), "r"(b))

#define MMA_BF16(d, a0, a1, a2, a3, b0, b1) \
    asm volatile("mma.sync.aligned.m16n8k16.row.col.f32.bf16.bf16.f32 " \
                 "{%0,%1,%2,%3}, {%4,%5,%6,%7}, {%8,%9}, {%0,%1,%2,%3};" \
                 : "+f"((d)[0]), "+f"((d)[1]), "+f"((d)[2]), "+f"((d)[3]) \
                 : "r"(a0), "r"(a1), "r"(a2), "r"(a3), "r"(b0), "r"(b1))

// ---------------------------------------------------------------------------
// Kernel 1: LayerNorm + projections, TR=8 rows/CTA for 2x grid parallelism.
// grid = (BN/8)*2; half 0 -> U fp32, half 1 -> V bf16. Weight chunk loaded
// coalesced and transposed through smem (stride-68 rows).
// ---------------------------------------------------------------------------
extern __shared__ float prep_dsm[];

__global__ void __launch_bounds__(256) prep_kernel(
    const float* __restrict__ h_res,
    const float* __restrict__ ln_w, const float* __restrict__ ln_b,
    const float* __restrict__ wu_w, const float* __restrict__ wu_b,
    const float* __restrict__ wv_w, const float* __restrict__ wv_b)
{
    float* sh = prep_dsm;                 // TR*512 floats
    float* Ws = prep_dsm + TR * D_MODEL;  // CHK*68 floats

    int t    = threadIdx.x;
    int warp = t >> 5;
    int lane = t & 31;
    int rb   = blockIdx.x >> 1;
    int half = blockIdx.x & 1;

    if (blockIdx.x == 0) {
        if (t < 8) { g_ce[t] = 0.0; g_cnt[t] = 0u; }
        if (t == 8) g_done = 0u;
    }

    // ---- LayerNorm: warp = 1 row ----
    {
        int lr  = warp;
        size_t row = (size_t)rb * TR + lr;
        const float4* hp = reinterpret_cast<const float4*>(h_res) + row * (D_MODEL / 4);
        float4 a[4];
        #pragma unroll
        for (int q = 0; q < 4; q++) a[q] = hp[lane + 32 * q];
        float s = 0.0f, sq = 0.0f;
        #pragma unroll
        for (int q = 0; q < 4; q++) {
            s  += a[q].x + a[q].y + a[q].z + a[q].w;
            sq += a[q].x*a[q].x + a[q].y*a[q].y + a[q].z*a[q].z + a[q].w*a[q].w;
        }
        #pragma unroll
        for (int o = 16; o > 0; o >>= 1) {
            s  += __shfl_xor_sync(0xffffffffu, s,  o);
            sq += __shfl_xor_sync(0xffffffffu, sq, o);
        }
        float mu   = s * (1.0f / (float)D_MODEL);
        float var  = sq * (1.0f / (float)D_MODEL) - mu * mu;
        float istd = rsqrtf(var + LN_EPS);

        const float4* wp = reinterpret_cast<const float4*>(ln_w);
        const float4* bp = reinterpret_cast<const float4*>(ln_b);
        float4* shp = reinterpret_cast<float4*>(sh) + lr * (D_MODEL / 4);
        #pragma unroll
        for (int q = 0; q < 4; q++) {
            float4 w4 = wp[lane + 32 * q];
            float4 b4 = bp[lane + 32 * q];
            float4 nv;
            nv.x = (a[q].x - mu) * istd * w4.x + b4.x;
            nv.y = (a[q].y - mu) * istd * w4.y + b4.y;
            nv.z = (a[q].z - mu) * istd * w4.z + b4.z;
            nv.w = (a[q].w - mu) * istd * w4.w + b4.w;
            shp[lane + 32 * q] = nv;
        }
    }
    __syncthreads();

    // ---- GEMM: thread = (row ty, 2 cols at tx*2); 4 channel chunks ----
    const float* wsrc = (half == 0) ? wu_w : wv_w;
    int ty = t >> 5;            // 0..7 row
    int tx = t & 31;            // 0..31 col pair

    float a0 = 0.0f, a1 = 0.0f;

    for (int cc = 0; cc < D_MODEL; cc += CHK) {
        #pragma unroll
        for (int it = 0; it < (D_LOW * CHK) / 256; it++) {
            int idx = t + it * 256;
            int c = idx & (CHK - 1);
            int o = idx >> 7;
            Ws[c * 68 + o] = wsrc[(size_t)o * D_MODEL + cc + c];
        }
        __syncthreads();

        const float* shr = sh + ty * D_MODEL + cc;
        #pragma unroll 4
        for (int c = 0; c < CHK; c++) {
            float2 w = *reinterpret_cast<const float2*>(Ws + c * 68 + tx * 2);
            float h = shr[c];
            a0 = fmaf(h, w.x, a0);
            a1 = fmaf(h, w.y, a1);
        }
        __syncthreads();
    }

    size_t grow = (size_t)rb * TR + ty;
    int lcol = tx * 2;
    if (half == 0) {
        float2 b = *reinterpret_cast<const float2*>(wu_b + lcol);
        *reinterpret_cast<float2*>(g_U + grow * D_LOW + lcol) =
            make_float2(a0 + b.x, a1 + b.y);
    } else {
        float2 b = *reinterpret_cast<const float2*>(wv_b + lcol);
        float v0 = a0 + b.x, v1 = a1 + b.y;
        uint32_t w; CVT_BF2(w, v0, v1);
        reinterpret_cast<uint32_t*>(g_Vb)[grow * 32 + tx] = w;
    }
}

// ---------------------------------------------------------------------------
// Kernel 2: mma.sync bilinear, FOUR tokens per CTA sharing each staged V
// chunk (byte-identical to the 75.9us R13 version). Last CTA finalizes.
// ---------------------------------------------------------------------------
#define DSTRIDE 41            // floats per D row (odd -> conflict-free scalar LDS)
#define VW 36                 // words per s_V row (9 uint4)

__global__ void __launch_bounds__(128) main_kernel(
    const float* __restrict__ x_true, const float* __restrict__ pad,
    const float* __restrict__ wb_w,  const float* __restrict__ wb_b,
    int B, int N, float* __restrict__ out, int total_ctas)
{
    __shared__ uint4 s_V[JT * 9];                 // 18432 B
    __shared__ float s_D[4][32 * DSTRIDE];        // 20992 B
    __shared__ uint32_t s_Wb[NB_PAD * 32];        // 5120 B
    __shared__ uint32_t s_U[TOK * 32];            // 4 tokens x 32 bf16x2
    __shared__ float s_wbb[NB_PAD];
    __shared__ float s_xi[TOK * 4];               // 4 tokens x (x,y,z,pad)
    __shared__ float s_red[4];
    __shared__ unsigned s_redc[4];

    int tid  = threadIdx.x;
    int wid  = tid >> 5;
    int lane = tid & 31;
    int g    = lane >> 2;       // group row (0..7)
    int tig  = lane & 3;        // thread in group (0..3)
    int r0 = blockIdx.x * TOK;  // first token row (b*N + i); N % TOK == 0
    int b  = r0 / N;

    for (int idx = tid; idx < NB_PAD * 32; idx += 128) {
        int row = idx >> 5, cp = idx & 31;
        float f0 = 0.0f, f1 = 0.0f;
        if (row < NUM_BINS) {
            f0 = wb_w[row * D_LOW + cp * 2];
            f1 = wb_w[row * D_LOW + cp * 2 + 1];
        }
        uint32_t v; CVT_BF2(v, f0, f1);
        s_Wb[idx] = v;
    }
    if (tid < TOK * 32) {
        int tok = tid >> 5, w = tid & 31;
        float f0 = g_U[(size_t)(r0 + tok) * D_LOW + w * 2];
        float f1 = g_U[(size_t)(r0 + tok) * D_LOW + w * 2 + 1];
        uint32_t v; CVT_BF2(v, f0, f1);
        s_U[tid] = v;
    }
    if (tid < NB_PAD) s_wbb[tid] = (tid < NUM_BINS) ? wb_b[tid] : 0.0f;
    if (tid < TOK) {
        size_t xb = (size_t)(r0 + tid) * 3;
        s_xi[tid * 4 + 0] = x_true[xb];
        s_xi[tid * 4 + 1] = x_true[xb + 1];
        s_xi[tid * 4 + 2] = x_true[xb + 2];
        s_xi[tid * 4 + 3] = pad[r0 + tid];
    }
    __syncthreads();

    // B fragments (constant across all chunks and tokens)
    uint32_t breg[40];
    #pragma unroll
    for (int ks = 0; ks < 4; ks++) {
        #pragma unroll
        for (int nt = 0; nt < 5; nt++) {
            int row = nt * 8 + g;
            int cp  = ks * 8 + tig;
            breg[ks * 10 + nt * 2 + 0] = s_Wb[row * 32 + cp];
            breg[ks * 10 + nt * 2 + 1] = s_Wb[row * 32 + cp + 4];
        }
    }
    // bias for this lane's D columns
    float bias0[5], bias1[5];
    #pragma unroll
    for (int nt = 0; nt < 5; nt++) {
        bias0[nt] = s_wbb[nt * 8 + 2 * tig];
        bias1[nt] = s_wbb[nt * 8 + 2 * tig + 1];
    }

    float* sDw = s_D[wid];
    const uint32_t* sv32 = reinterpret_cast<const uint32_t*>(s_V);

    float cv = 0.0f; unsigned cc = 0u;
    int nchunks = (N + JT - 1) / JT;

    for (int jc = 0; jc < nchunks; jc++) {
        __syncwarp();
        int jw = jc * JT + wid * 32;      // this warp's first j

        // stage V rows jw..jw+31 (coalesced: 8 lanes per 128B row)
        {
            const uint4* src = reinterpret_cast<const uint4*>(g_Vb) + ((size_t)b * N) * 8;
            #pragma unroll
            for (int it = 0; it < 8; it++) {
                int idx = it * 32 + lane;
                int row = idx >> 3, q = idx & 7;
                int j = jw + row;
                uint4 v = make_uint4(0u, 0u, 0u, 0u);
                if (j < N) v = src[(size_t)j * 8 + q];
                s_V[(wid * 32 + row) * 9 + q] = v;
            }
        }

        // j-coordinates loaded once, reused by all tokens
        int j = jw + lane;
        float xj0 = 0.f, xj1 = 0.f, xj2 = 0.f, pj = 0.f;
        if (j < N) {
            size_t xb = ((size_t)b * N + j) * 3;
            xj0 = x_true[xb]; xj1 = x_true[xb + 1]; xj2 = x_true[xb + 2];
            pj = pad[(size_t)b * N + j];
        }
        __syncwarp();

        #pragma unroll
        for (int tok = 0; tok < TOK; tok++) {
            // U words for this token (from smem; keeps register count flat)
            uint32_t ureg[8];
            #pragma unroll
            for (int ks = 0; ks < 4; ks++) {
                ureg[2 * ks + 0] = s_U[tok * 32 + ks * 8 + tig];
                ureg[2 * ks + 1] = s_U[tok * 32 + ks * 8 + tig + 4];
            }

            // acc init = bias (folds wb_b into the GEMM)
            float acc[2][5][4];
            #pragma unroll
            for (int m = 0; m < 2; m++)
                #pragma unroll
                for (int nt = 0; nt < 5; nt++) {
                    acc[m][nt][0] = bias0[nt];
                    acc[m][nt][1] = bias1[nt];
                    acc[m][nt][2] = bias0[nt];
                    acc[m][nt][3] = bias1[nt];
                }

            // A-fragments: V word (conflict-free LDS.32) * U word
            #pragma unroll
            for (int m = 0; m < 2; m++) {
                int row0 = wid * 32 + m * 16 + g;
                #pragma unroll
                for (int ks = 0; ks < 4; ks++) {
                    int w0 = row0 * VW + ks * 8 + tig;
                    uint32_t a0 = sv32[w0];
                    uint32_t a1 = sv32[w0 + 8 * VW];
                    uint32_t a2 = sv32[w0 + 4];
                    uint32_t a3 = sv32[w0 + 8 * VW + 4];
                    MULBF2(a0, a0, ureg[2 * ks]);
                    MULBF2(a1, a1, ureg[2 * ks]);
                    MULBF2(a2, a2, ureg[2 * ks + 1]);
                    MULBF2(a3, a3, ureg[2 * ks + 1]);
                    #pragma unroll
                    for (int nt = 0; nt < 5; nt++)
                        MMA_BF16(acc[m][nt], a0, a1, a2, a3,
                                 breg[ks * 10 + nt * 2], breg[ks * 10 + nt * 2 + 1]);
                }
            }
            __syncwarp();

            // D -> smem (pair-major, 41-float stride)
            #pragma unroll
            for (int m = 0; m < 2; m++) {
                int p0 = m * 16 + g;
                #pragma unroll
                for (int nt = 0; nt < 5; nt++) {
                    int col = nt * 8 + tig * 2;
                    sDw[p0 * DSTRIDE + col]           = acc[m][nt][0];
                    sDw[p0 * DSTRIDE + col + 1]       = acc[m][nt][1];
                    sDw[(p0 + 8) * DSTRIDE + col]     = acc[m][nt][2];
                    sDw[(p0 + 8) * DSTRIDE + col + 1] = acc[m][nt][3];
                }
            }
            __syncwarp();

            // epilogue: pair = lane, single-pass maxless logsumexp
            const float* lrow = sDw + lane * DSTRIDE;
            float xi0 = s_xi[tok * 4 + 0];
            float xi1 = s_xi[tok * 4 + 1];
            float xi2 = s_xi[tok * 4 + 2];
            float pi  = s_xi[tok * 4 + 3];
            float dx = xi0 - xj0, dy = xi1 - xj1, dz = xi2 - xj2;
            float dist = sqrtf(dx * dx + dy * dy + dz * dz);
            int bin = (int)((dist - DIST_MIN_F) / BIN_W);
            bin = min(max(bin, 0), NUM_BINS - 1);

            float ssum = 0.0f, tl = 0.0f;
            #pragma unroll
            for (int k = 0; k < NUM_BINS; k++) {
                float lv = lrow[k];
                ssum += __expf(lv);
                if (k == bin) tl = lv;
            }
            float ce = __logf(ssum) - tl;

            bool ok = (j < N) && (pi * pj > 0.0f);
            cv += ok ? ce : 0.0f;
            cc += ok ? 1u : 0u;
            __syncwarp();
        }
    }

    #pragma unroll
    for (int o = 16; o > 0; o >>= 1) {
        cv += __shfl_down_sync(0xffffffffu, cv, o);
        cc += __shfl_down_sync(0xffffffffu, cc, o);
    }
    if (lane == 0) { s_red[wid] = cv; s_redc[wid] = cc; }
    __syncthreads();
    if (tid == 0) {
        float S = s_red[0] + s_red[1] + s_red[2] + s_red[3];
        unsigned C = s_redc[0] + s_redc[1] + s_redc[2] + s_redc[3];
        atomicAdd(&g_ce[b], (double)S);
        atomicAdd(&g_cnt[b], C);
        __threadfence();
        unsigned done = atomicAdd(&g_done, 1u);
        if (done == (unsigned)(total_ctas - 1)) {
            __threadfence();
            double loss = 0.0;
            int valid = 0;
            for (int bb = 0; bb < B; bb++) {
                if (g_cnt[bb] > 0u) { loss += g_ce[bb] / (double)g_cnt[bb]; valid++; }
            }
            out[0] = (float)(valid > 0 ? loss / (double)valid : 0.0);
        }
    }
}

// ---------------------------------------------------------------------------
extern "C" void kernel_launch(void* const* d_in, const int* in_sizes, int n_in,
                              void* d_out, int out_size)
{
    const float* h_res  = (const float*)d_in[0];
    const float* x_true = (const float*)d_in[1];
    const float* padm   = (const float*)d_in[2];
    const float* ln_w   = (const float*)d_in[3];
    const float* ln_b   = (const float*)d_in[4];
    const float* wu_w   = (const float*)d_in[5];
    const float* wu_b   = (const float*)d_in[6];
    const float* wv_w   = (const float*)d_in[7];
    const float* wv_b   = (const float*)d_in[8];
    const float* wb_w   = (const float*)d_in[9];
    const float* wb_b   = (const float*)d_in[10];

    int BN = in_sizes[0] / D_MODEL;   // B*N
    int B = 2;
    int N = BN / B;

    const int prep_smem = (TR * D_MODEL + CHK * 68) * (int)sizeof(float);  // ~50.8 KB
    cudaFuncSetAttribute(prep_kernel, cudaFuncAttributeMaxDynamicSharedMemorySize, prep_smem);

    prep_kernel<<<(BN / TR) * 2, 256, prep_smem>>>(h_res, ln_w, ln_b,
                                                   wu_w, wu_b, wv_w, wv_b);

    main_kernel<<<BN / TOK, 128>>>(x_true, padm, wb_w, wb_b, B, N, (float*)d_out, BN / TOK);
}

// round 16
// speedup vs baseline: 1.1746x; 1.0788x over previous
#include <cuda_runtime.h>
#include <cuda_bf16.h>
#include <math.h>
#include <stdint.h>

#define D_MODEL 512
#define D_LOW   64
#define NUM_BINS 39
#define NB_PAD  40
#define DIST_MIN_F 2.0f
#define DIST_MAX_F 22.0f
#define BIN_W  ((DIST_MAX_F - DIST_MIN_F) / (float)(NUM_BINS - 1))
#define LN_EPS 1e-5f
#define MAX_ROWS 4096
#define JT 128
#define TOK 4                  // tokens per CTA (main phase)
#define PTR 8                  // rows per CTA (prep phase)
#define CHK 128                // channel chunk (prep weight tile)

__device__ float g_U[MAX_ROWS * D_LOW];
__device__ unsigned long long g_Vb[MAX_ROWS * (D_LOW / 4)];  // 4 bf16 per u64
__device__ double g_ce[8];
__device__ unsigned int g_cnt[8];
__device__ unsigned int g_done;
__device__ unsigned int g_sync;

#define CVT_BF2(res, lo, hi) \
    asm("cvt.rn.satfinite.bf16x2.f32 %0, %1, %2;" : "=r"(res) : "f"(hi), "f"(lo))
#define MULBF2(res, a, b) \
    asm("mul.bf16x2 %0, %1, %2;" : "=r"(res) : "r"(a), "r"(b))

#define MMA_BF16(d, a0, a1, a2, a3, b0, b1) \
    asm volatile("mma.sync.aligned.m16n8k16.row.col.f32.bf16.bf16.f32 " \
                 "{%0,%1,%2,%3}, {%4,%5,%6,%7}, {%8,%9}, {%0,%1,%2,%3};" \
                 : "+f"((d)[0]), "+f"((d)[1]), "+f"((d)[2]), "+f"((d)[3]) \
                 : "r"(a0), "r"(a1), "r"(a2), "r"(a3), "r"(b0), "r"(b1))

#define DSTRIDE 41            // floats per D row (odd -> conflict-free scalar LDS)
#define VW 36                 // words per s_V row (9 uint4)

// dynamic smem layout (floats):
//   phase 1: sh[0..4096) = 8x512, Ws[4096..4096+CHK*68)
//   phase 2: s_V[0..4608) (1152 uint4), s_D[4608..9856) (4x32x41),
//            s_Wb[9856..11136), s_U[11136..11264), s_wbb[11264..11304),
//            s_xi[11304..11320), s_red[11320..11324), s_redc[11324..11328)
#define DSM_FLOATS (PTR * D_MODEL + CHK * 68)     // 12800 floats = 51200 B

extern __shared__ float dsm[];

__global__ void __launch_bounds__(128, 3) fused_kernel(
    const float* __restrict__ h_res,
    const float* __restrict__ x_true, const float* __restrict__ pad,
    const float* __restrict__ ln_w, const float* __restrict__ ln_b,
    const float* __restrict__ wu_w, const float* __restrict__ wu_b,
    const float* __restrict__ wv_w, const float* __restrict__ wv_b,
    const float* __restrict__ wb_w, const float* __restrict__ wb_b,
    int B, int N, float* __restrict__ out, int total_ctas)
{
    int tid  = threadIdx.x;
    int wid  = tid >> 5;
    int lane = tid & 31;

    // =====================================================================
    // PHASE 1: LayerNorm + projection for this CTA's unit (8 rows x 1 half)
    // =====================================================================
    {
        float* sh = dsm;                   // 8*512
        float* Ws = dsm + PTR * D_MODEL;   // CHK*68

        int rb   = blockIdx.x >> 1;
        int half = blockIdx.x & 1;

        // LN: warp = 2 rows
        #pragma unroll
        for (int rr = 0; rr < 2; rr++) {
            int lr  = wid * 2 + rr;
            size_t row = (size_t)rb * PTR + lr;
            const float4* hp = reinterpret_cast<const float4*>(h_res) + row * (D_MODEL / 4);
            float4 a[4];
            #pragma unroll
            for (int q = 0; q < 4; q++) a[q] = hp[lane + 32 * q];
            float s = 0.0f, sq = 0.0f;
            #pragma unroll
            for (int q = 0; q < 4; q++) {
                s  += a[q].x + a[q].y + a[q].z + a[q].w;
                sq += a[q].x*a[q].x + a[q].y*a[q].y + a[q].z*a[q].z + a[q].w*a[q].w;
            }
            #pragma unroll
            for (int o = 16; o > 0; o >>= 1) {
                s  += __shfl_xor_sync(0xffffffffu, s,  o);
                sq += __shfl_xor_sync(0xffffffffu, sq, o);
            }
            float mu   = s * (1.0f / (float)D_MODEL);
            float var  = sq * (1.0f / (float)D_MODEL) - mu * mu;
            float istd = rsqrtf(var + LN_EPS);

            const float4* wp = reinterpret_cast<const float4*>(ln_w);
            const float4* bp = reinterpret_cast<const float4*>(ln_b);
            float4* shp = reinterpret_cast<float4*>(sh) + lr * (D_MODEL / 4);
            #pragma unroll
            for (int q = 0; q < 4; q++) {
                float4 w4 = wp[lane + 32 * q];
                float4 b4 = bp[lane + 32 * q];
                float4 nv;
                nv.x = (a[q].x - mu) * istd * w4.x + b4.x;
                nv.y = (a[q].y - mu) * istd * w4.y + b4.y;
                nv.z = (a[q].z - mu) * istd * w4.z + b4.z;
                nv.w = (a[q].w - mu) * istd * w4.w + b4.w;
                shp[lane + 32 * q] = nv;
            }
        }
        __syncthreads();

        // GEMM: thread = (row ty=t>>4, 4 cols at (t&15)*4); 4 channel chunks
        const float* wsrc = (half == 0) ? wu_w : wv_w;
        int ty = tid >> 4;
        int tx = tid & 15;

        float a0 = 0.0f, a1 = 0.0f, a2 = 0.0f, a3 = 0.0f;

        for (int cc = 0; cc < D_MODEL; cc += CHK) {
            #pragma unroll
            for (int it = 0; it < (D_LOW * CHK) / 128; it++) {
                int idx = tid + it * 128;
                int c = idx & (CHK - 1);
                int o = idx >> 7;
                Ws[c * 68 + o] = wsrc[(size_t)o * D_MODEL + cc + c];
            }
            __syncthreads();

            const float* shr = sh + ty * D_MODEL + cc;
            #pragma unroll 4
            for (int c = 0; c < CHK; c++) {
                float4 w = *reinterpret_cast<const float4*>(Ws + c * 68 + tx * 4);
                float h = shr[c];
                a0 = fmaf(h, w.x, a0);
                a1 = fmaf(h, w.y, a1);
                a2 = fmaf(h, w.z, a2);
                a3 = fmaf(h, w.w, a3);
            }
            __syncthreads();
        }

        size_t grow = (size_t)rb * PTR + ty;
        int lcol = tx * 4;
        if (half == 0) {
            float4 b = *reinterpret_cast<const float4*>(wu_b + lcol);
            *reinterpret_cast<float4*>(g_U + grow * D_LOW + lcol) =
                make_float4(a0 + b.x, a1 + b.y, a2 + b.z, a3 + b.w);
        } else {
            float4 b = *reinterpret_cast<const float4*>(wv_b + lcol);
            float v0 = a0 + b.x, v1 = a1 + b.y, v2 = a2 + b.z, v3 = a3 + b.w;
            uint32_t lo, hi;
            CVT_BF2(lo, v0, v1); CVT_BF2(hi, v2, v3);
            g_Vb[grow * 16 + (lcol >> 2)] =
                (unsigned long long)lo | ((unsigned long long)hi << 32);
        }
    }

    // =====================================================================
    // GLOBAL BARRIER (all 384 CTAs guaranteed resident via launch_bounds)
    // =====================================================================
    __threadfence();
    __syncthreads();
    if (tid == 0) {
        atomicAdd(&g_sync, 1u);
        while (*((volatile unsigned int*)&g_sync) < (unsigned)total_ctas) { }
    }
    __syncthreads();

    // =====================================================================
    // PHASE 2: mma.sync bilinear + softmax-CE (identical to 48.6us main)
    // =====================================================================
    uint4*    s_V   = reinterpret_cast<uint4*>(dsm);
    float*    s_D   = dsm + 4608;
    uint32_t* s_Wb  = reinterpret_cast<uint32_t*>(dsm + 9856);
    uint32_t* s_U   = reinterpret_cast<uint32_t*>(dsm + 11136);
    float*    s_wbb = dsm + 11264;
    float*    s_xi  = dsm + 11304;
    float*    s_red = dsm + 11320;
    unsigned* s_redc = reinterpret_cast<unsigned*>(dsm + 11324);

    int g   = lane >> 2;
    int tig = lane & 3;
    int r0 = blockIdx.x * TOK;
    int b  = r0 / N;

    for (int idx = tid; idx < NB_PAD * 32; idx += 128) {
        int row = idx >> 5, cp = idx & 31;
        float f0 = 0.0f, f1 = 0.0f;
        if (row < NUM_BINS) {
            f0 = wb_w[row * D_LOW + cp * 2];
            f1 = wb_w[row * D_LOW + cp * 2 + 1];
        }
        uint32_t v; CVT_BF2(v, f0, f1);
        s_Wb[idx] = v;
    }
    if (tid < TOK * 32) {
        int tok = tid >> 5, w = tid & 31;
        float f0 = g_U[(size_t)(r0 + tok) * D_LOW + w * 2];
        float f1 = g_U[(size_t)(r0 + tok) * D_LOW + w * 2 + 1];
        uint32_t v; CVT_BF2(v, f0, f1);
        s_U[tid] = v;
    }
    if (tid < NB_PAD) s_wbb[tid] = (tid < NUM_BINS) ? wb_b[tid] : 0.0f;
    if (tid < TOK) {
        size_t xb = (size_t)(r0 + tid) * 3;
        s_xi[tid * 4 + 0] = x_true[xb];
        s_xi[tid * 4 + 1] = x_true[xb + 1];
        s_xi[tid * 4 + 2] = x_true[xb + 2];
        s_xi[tid * 4 + 3] = pad[r0 + tid];
    }
    __syncthreads();

    uint32_t breg[40];
    #pragma unroll
    for (int ks = 0; ks < 4; ks++) {
        #pragma unroll
        for (int nt = 0; nt < 5; nt++) {
            int row = nt * 8 + g;
            int cp  = ks * 8 + tig;
            breg[ks * 10 + nt * 2 + 0] = s_Wb[row * 32 + cp];
            breg[ks * 10 + nt * 2 + 1] = s_Wb[row * 32 + cp + 4];
        }
    }
    float bias0[5], bias1[5];
    #pragma unroll
    for (int nt = 0; nt < 5; nt++) {
        bias0[nt] = s_wbb[nt * 8 + 2 * tig];
        bias1[nt] = s_wbb[nt * 8 + 2 * tig + 1];
    }

    float* sDw = s_D + wid * (32 * DSTRIDE);
    const uint32_t* sv32 = reinterpret_cast<const uint32_t*>(s_V);

    float cv = 0.0f; unsigned cc = 0u;
    int nchunks = (N + JT - 1) / JT;

    for (int jc = 0; jc < nchunks; jc++) {
        __syncwarp();
        int jw = jc * JT + wid * 32;

        {
            const uint4* src = reinterpret_cast<const uint4*>(g_Vb) + ((size_t)b * N) * 8;
            #pragma unroll
            for (int it = 0; it < 8; it++) {
                int idx = it * 32 + lane;
                int row = idx >> 3, q = idx & 7;
                int j = jw + row;
                uint4 v = make_uint4(0u, 0u, 0u, 0u);
                if (j < N) v = src[(size_t)j * 8 + q];
                s_V[(wid * 32 + row) * 9 + q] = v;
            }
        }

        int j = jw + lane;
        float xj0 = 0.f, xj1 = 0.f, xj2 = 0.f, pj = 0.f;
        if (j < N) {
            size_t xb = ((size_t)b * N + j) * 3;
            xj0 = x_true[xb]; xj1 = x_true[xb + 1]; xj2 = x_true[xb + 2];
            pj = pad[(size_t)b * N + j];
        }
        __syncwarp();

        #pragma unroll
        for (int tok = 0; tok < TOK; tok++) {
            uint32_t ureg[8];
            #pragma unroll
            for (int ks = 0; ks < 4; ks++) {
                ureg[2 * ks + 0] = s_U[tok * 32 + ks * 8 + tig];
                ureg[2 * ks + 1] = s_U[tok * 32 + ks * 8 + tig + 4];
            }

            float acc[2][5][4];
            #pragma unroll
            for (int m = 0; m < 2; m++)
                #pragma unroll
                for (int nt = 0; nt < 5; nt++) {
                    acc[m][nt][0] = bias0[nt];
                    acc[m][nt][1] = bias1[nt];
                    acc[m][nt][2] = bias0[nt];
                    acc[m][nt][3] = bias1[nt];
                }

            #pragma unroll
            for (int m = 0; m < 2; m++) {
                int row0 = wid * 32 + m * 16 + g;
                #pragma unroll
                for (int ks = 0; ks < 4; ks++) {
                    int w0 = row0 * VW + ks * 8 + tig;
                    uint32_t a0 = sv32[w0];
                    uint32_t a1 = sv32[w0 + 8 * VW];
                    uint32_t a2 = sv32[w0 + 4];
                    uint32_t a3 = sv32[w0 + 8 * VW + 4];
                    MULBF2(a0, a0, ureg[2 * ks]);
                    MULBF2(a1, a1, ureg[2 * ks]);
                    MULBF2(a2, a2, ureg[2 * ks + 1]);
                    MULBF2(a3, a3, ureg[2 * ks + 1]);
                    #pragma unroll
                    for (int nt = 0; nt < 5; nt++)
                        MMA_BF16(acc[m][nt], a0, a1, a2, a3,
                                 breg[ks * 10 + nt * 2], breg[ks * 10 + nt * 2 + 1]);
                }
            }
            __syncwarp();

            #pragma unroll
            for (int m = 0; m < 2; m++) {
                int p0 = m * 16 + g;
                #pragma unroll
                for (int nt = 0; nt < 5; nt++) {
                    int col = nt * 8 + tig * 2;
                    sDw[p0 * DSTRIDE + col]           = acc[m][nt][0];
                    sDw[p0 * DSTRIDE + col + 1]       = acc[m][nt][1];
                    sDw[(p0 + 8) * DSTRIDE + col]     = acc[m][nt][2];
                    sDw[(p0 + 8) * DSTRIDE + col + 1] = acc[m][nt][3];
                }
            }
            __syncwarp();

            const float* lrow = sDw + lane * DSTRIDE;
            float xi0 = s_xi[tok * 4 + 0];
            float xi1 = s_xi[tok * 4 + 1];
            float xi2 = s_xi[tok * 4 + 2];
            float pi  = s_xi[tok * 4 + 3];
            float dx = xi0 - xj0, dy = xi1 - xj1, dz = xi2 - xj2;
            float dist = sqrtf(dx * dx + dy * dy + dz * dz);
            int bin = (int)((dist - DIST_MIN_F) / BIN_W);
            bin = min(max(bin, 0), NUM_BINS - 1);

            float ssum = 0.0f, tl = 0.0f;
            #pragma unroll
            for (int k = 0; k < NUM_BINS; k++) {
                float lv = lrow[k];
                ssum += __expf(lv);
                if (k == bin) tl = lv;
            }
            float ce = __logf(ssum) - tl;

            bool ok = (j < N) && (pi * pj > 0.0f);
            cv += ok ? ce : 0.0f;
            cc += ok ? 1u : 0u;
            __syncwarp();
        }
    }

    #pragma unroll
    for (int o = 16; o > 0; o >>= 1) {
        cv += __shfl_down_sync(0xffffffffu, cv, o);
        cc += __shfl_down_sync(0xffffffffu, cc, o);
    }
    if (lane == 0) { s_red[wid] = cv; s_redc[wid] = cc; }
    __syncthreads();
    if (tid == 0) {
        float S = s_red[0] + s_red[1] + s_red[2] + s_red[3];
        unsigned C = s_redc[0] + s_redc[1] + s_redc[2] + s_redc[3];
        atomicAdd(&g_ce[b], (double)S);
        atomicAdd(&g_cnt[b], C);
        __threadfence();
        unsigned done = atomicAdd(&g_done, 1u);
        if (done == (unsigned)(total_ctas - 1)) {
            __threadfence();
            double loss = 0.0;
            int valid = 0;
            for (int bb = 0; bb < B; bb++) {
                if (g_cnt[bb] > 0u) { loss += g_ce[bb] / (double)g_cnt[bb]; valid++; }
            }
            out[0] = (float)(valid > 0 ? loss / (double)valid : 0.0);
            // self-reset for next graph replay (this CTA is provably last)
            #pragma unroll
            for (int bb = 0; bb < 8; bb++) { g_ce[bb] = 0.0; g_cnt[bb] = 0u; }
            g_done = 0u;
            g_sync = 0u;
            __threadfence();
        }
    }
}

// ---------------------------------------------------------------------------
extern "C" void kernel_launch(void* const* d_in, const int* in_sizes, int n_in,
                              void* d_out, int out_size)
{
    const float* h_res  = (const float*)d_in[0];
    const float* x_true = (const float*)d_in[1];
    const float* padm   = (const float*)d_in[2];
    const float* ln_w   = (const float*)d_in[3];
    const float* ln_b   = (const float*)d_in[4];
    const float* wu_w   = (const float*)d_in[5];
    const float* wu_b   = (const float*)d_in[6];
    const float* wv_w   = (const float*)d_in[7];
    const float* wv_b   = (const float*)d_in[8];
    const float* wb_w   = (const float*)d_in[9];
    const float* wb_b   = (const float*)d_in[10];

    int BN = in_sizes[0] / D_MODEL;   // B*N
    int B = 2;
    int N = BN / B;
    int grid = BN / TOK;              // 384; == (BN/PTR)*2 prep units

    const int dsm_bytes = DSM_FLOATS * (int)sizeof(float);   // 51200 B
    cudaFuncSetAttribute(fused_kernel, cudaFuncAttributeMaxDynamicSharedMemorySize, dsm_bytes);

    fused_kernel<<<grid, 128, dsm_bytes>>>(h_res, x_true, padm, ln_w, ln_b,
                                           wu_w, wu_b, wv_w, wv_b, wb_w, wb_b,
                                           B, N, (float*)d_out, grid);
}